// round 3
// baseline (speedup 1.0000x reference)
#include <cuda_runtime.h>

#define NTOT 50000
#define AANCH 32
#define DDIM 64
#define NG 3125          // NTOT/16
#define BR 128
#define THREADS 128
#define XS_STRIDE 130
#define OS_STRIDE 65
#define GU 32            // u-groups per prep block
#define NB_G ((NG + GU - 1) / GU)   // 98

// P' dup pairs: g_Cdup[a*128 + 2k {,+1}] = (1/32) * embeds[anchor[a]] . W1[k,:]
__device__ __align__(16) float g_Cdup[AANCH * 2 * DDIM];
// g_G[u*64+k] = (1/32) * (sum of embeds rows 16u..16u+15) . W2[k,:] + 0.5*b[k]
__device__ __align__(16) float g_G[NG * DDIM];

typedef unsigned long long u64;

__device__ __forceinline__ u64 pack2(float x, float y) {
    u64 r; asm("mov.b64 %0, {%1,%2};" : "=l"(r) : "f"(x), "f"(y)); return r;
}
__device__ __forceinline__ void unpack2(u64 v, float& x, float& y) {
    asm("mov.b64 {%0,%1}, %2;" : "=f"(x), "=f"(y) : "l"(v));
}
__device__ __forceinline__ u64 fma2(u64 a, u64 b, u64 c) {
    u64 d; asm("fma.rn.f32x2 %0, %1, %2, %3;" : "=l"(d) : "l"(a), "l"(b), "l"(c)); return d;
}

// ---------------------------------------------------------------------------
// prep: blocks [0, NB_G): G rows (fused 16-row reduce + 64x64 matmul).
//       block NB_G: P' (anchor projections, dup-pair layout).
// ---------------------------------------------------------------------------
__global__ __launch_bounds__(256) void prep_kernel(
    const float* __restrict__ embeds,
    const int* __restrict__ anchor,
    const float* __restrict__ Wh,
    const float* __restrict__ bias)
{
    __shared__ float Ws[DDIM * 65];   // W2 (G path) or W1 (P' path), [k][d]
    __shared__ float Es[GU * 65];     // E16 rows or anchor embeds, [i][d]
    const int tid = threadIdx.x;

    if (blockIdx.x < NB_G) {
        const int u0 = blockIdx.x * GU;
        // stage W2[k][d] = Wh[k*128 + 64 + d]
        #pragma unroll
        for (int i = 0; i < 16; i++) {
            int idx = tid + i * 256;
            int k = idx >> 6, d = idx & 63;
            Ws[k * 65 + d] = Wh[k * 2 * DDIM + DDIM + d];
        }
        // fused reduce: Es[ul][4c..4c+3] = sum_{j<16} embeds[16(u0+ul)+j][4c..]
        #pragma unroll
        for (int i = 0; i < 2; i++) {
            int s = tid + i * 256;
            int ul = s >> 4, c = s & 15;
            int u = u0 + ul;
            if (u < NG) {
                const float4* src = (const float4*)(embeds + (size_t)(16 * u) * DDIM) + c;
                float4 a = make_float4(0.f, 0.f, 0.f, 0.f);
                #pragma unroll
                for (int j = 0; j < 16; j++) {
                    float4 v = src[j * 16];
                    a.x += v.x; a.y += v.y; a.z += v.z; a.w += v.w;
                }
                Es[ul * 65 + 4 * c + 0] = a.x;
                Es[ul * 65 + 4 * c + 1] = a.y;
                Es[ul * 65 + 4 * c + 2] = a.z;
                Es[ul * 65 + 4 * c + 3] = a.w;
            }
        }
        __syncthreads();
        // matmul: thread -> (iu, 8 cols kbase..kbase+7)
        int iu = tid >> 3;
        int kbase = (tid & 7) * 8;
        int u = u0 + iu;
        float s[8];
        #pragma unroll
        for (int kk = 0; kk < 8; kk++) s[kk] = 0.f;
        #pragma unroll 8
        for (int d = 0; d < DDIM; d++) {
            float e = Es[iu * 65 + d];
            #pragma unroll
            for (int kk = 0; kk < 8; kk++) s[kk] += e * Ws[(kbase + kk) * 65 + d];
        }
        if (u < NG) {
            #pragma unroll
            for (int kk = 0; kk < 8; kk++)
                g_G[u * DDIM + kbase + kk] =
                    s[kk] * (1.0f / 32.0f) + 0.5f * bias[kbase + kk];
        }
    } else {
        // P' path: stage W1 and the 32 anchor embed rows
        #pragma unroll
        for (int i = 0; i < 16; i++) {
            int idx = tid + i * 256;
            int k = idx >> 6, d = idx & 63;
            Ws[k * 65 + d] = Wh[k * 2 * DDIM + d];           // W1[k][d]
        }
        #pragma unroll
        for (int i = 0; i < 8; i++) {
            int idx = tid + i * 256;
            int a = idx >> 6, d = idx & 63;
            Es[a * 65 + d] = embeds[(size_t)anchor[a] * DDIM + d];
        }
        __syncthreads();
        int ia = tid >> 3;          // anchor 0..31
        int kbase = (tid & 7) * 8;
        float s[8];
        #pragma unroll
        for (int kk = 0; kk < 8; kk++) s[kk] = 0.f;
        #pragma unroll 8
        for (int d = 0; d < DDIM; d++) {
            float e = Es[ia * 65 + d];
            #pragma unroll
            for (int kk = 0; kk < 8; kk++) s[kk] += e * Ws[(kbase + kk) * 65 + d];
        }
        #pragma unroll
        for (int kk = 0; kk < 8; kk++) {
            float v = s[kk] * (1.0f / 32.0f);
            g_Cdup[ia * 2 * DDIM + 2 * (kbase + kk)]     = v;
            g_Cdup[ia * 2 * DDIM + 2 * (kbase + kk) + 1] = v;
        }
    }
}

// ---------------------------------------------------------------------------
// main: out[n,k] = sum_{a<32} dists[a,n]*P'[a,k] + G[u1(n),k] + G[u2(n),k]
//       u1 = (2n) % NG, u2 = (u1+1) % NG
// ---------------------------------------------------------------------------
__global__ __launch_bounds__(THREADS) void main_kernel(
    const float* __restrict__ dists,
    float* __restrict__ out)
{
    __shared__ float smem[BR * OS_STRIDE];               // 33.3 KB
    float* Xs = smem;                                    // [32][130]
    float* Cd = smem + AANCH * XS_STRIDE;                // [32][128] dup pairs
    const int tid = threadIdx.x;
    const int row0 = blockIdx.x * BR;

    const int cg = tid & 7;
    const int rg = tid >> 3;
    const int rbase = rg * 8;

    // stage P' dup pairs (L2-resident)
    {
        const float4* src = (const float4*)g_Cdup;
        float4* dst = (float4*)Cd;
        #pragma unroll
        for (int i = 0; i < (AANCH * 2 * DDIM / 4) / THREADS; i++)   // 8
            dst[tid + i * THREADS] = src[tid + i * THREADS];
    }
    // stage dists transposed: Xs[a][r] = dists[a*N + row0+r]
    #pragma unroll
    for (int i = 0; i < (AANCH * BR) / THREADS; i++) {               // 32
        int idx = tid + i * THREADS;
        int a = idx >> 7, r = idx & 127;
        int row = row0 + r; if (row >= NTOT) row = NTOT - 1;
        Xs[a * XS_STRIDE + r] = dists[(size_t)a * NTOT + row];
    }

    u64 acc[8][4];
    #pragma unroll
    for (int q = 0; q < 8; q++)
        #pragma unroll
        for (int p = 0; p < 4; p++) acc[q][p] = 0ULL;
    __syncthreads();

    const float* xcol = Xs + rbase;
    const float* ccol = Cd + cg * 2;
    #pragma unroll 4
    for (int j = 0; j < AANCH; j++) {
        u64 xv[4];
        #pragma unroll
        for (int p = 0; p < 4; p++)
            xv[p] = *(const u64*)(xcol + j * XS_STRIDE + 2 * p);     // rows (r, r+1)
        #pragma unroll
        for (int q = 0; q < 8; q++) {
            u64 cv = *(const u64*)(ccol + j * 2 * DDIM + 16 * q);    // (c, c)
            #pragma unroll
            for (int p = 0; p < 4; p++)
                acc[q][p] = fma2(xv[p], cv, acc[q][p]);
        }
    }
    __syncthreads();

    // transpose through shared (conflict-free, stride 65)
    float* Os = smem;
    #pragma unroll
    for (int q = 0; q < 8; q++) {
        int k = cg + 8 * q;
        #pragma unroll
        for (int p = 0; p < 4; p++) {
            float lo, hi; unpack2(acc[q][p], lo, hi);
            Os[(rbase + 2 * p) * OS_STRIDE + k] = lo;
            Os[(rbase + 2 * p + 1) * OS_STRIDE + k] = hi;
        }
    }
    __syncthreads();

    // epilogue: coalesced G row adds + store. Thread handles fixed k, r += 2/iter.
    int rows_here = NTOT - row0; if (rows_here > BR) rows_here = BR;
    int r = tid >> 6;                 // 0 or 1
    int k = tid & 63;
    int u1 = (2 * (row0 + r)) % NG;   // then += 4 per iter with wrap
    #pragma unroll 4
    for (int i = 0; i < BR / 2; i++, r += 2) {
        if (r < rows_here) {
            int u2 = u1 + 1; if (u2 == NG) u2 = 0;
            out[(size_t)(row0 + r) * DDIM + k] =
                Os[r * OS_STRIDE + k] + g_G[u1 * DDIM + k] + g_G[u2 * DDIM + k];
        }
        u1 += 4; if (u1 >= NG) u1 -= NG;
    }
}

// ---------------------------------------------------------------------------
extern "C" void kernel_launch(void* const* d_in, const int* in_sizes, int n_in,
                              void* d_out, int out_size)
{
    const float* embeds = (const float*)d_in[0];   // (N, D)
    const float* dists  = (const float*)d_in[1];   // (A, N)
    const int*   anchor = (const int*)d_in[2];     // (A,)
    const float* Wh     = (const float*)d_in[3];   // (D, 2D)
    const float* bias   = (const float*)d_in[4];   // (D,)
    float* out = (float*)d_out;
    (void)in_sizes; (void)n_in; (void)out_size;

    prep_kernel<<<NB_G + 1, 256>>>(embeds, anchor, Wh, bias);
    main_kernel<<<(NTOT + BR - 1) / BR, THREADS>>>(dists, out);
}

// round 4
// speedup vs baseline: 1.0779x; 1.0779x over previous
#include <cuda_runtime.h>

#define NTOT 50000
#define AANCH 32
#define DDIM 64
#define NG 3125           // NTOT/16
#define BR 64             // rows per main block
#define THREADS 128
#define XS_STRIDE 66
#define OS_STRIDE 65
#define NB4 ((NG + 3) / 4)   // 782 G-blocks in prep (4 u each)

// P' dup pairs: g_Cdup[a*128 + 2k {,+1}] = (1/32) * embeds[anchor[a]] . W1[k,:]
__device__ __align__(16) float g_Cdup[AANCH * 2 * DDIM];
// g_G[u*64+k] = (1/32) * (sum embeds rows 16u..16u+15) . W2[k,:] + 0.5*b[k]
__device__ __align__(16) float g_G[NG * DDIM];

typedef unsigned long long u64;

__device__ __forceinline__ void unpack2(u64 v, float& x, float& y) {
    asm("mov.b64 {%0,%1}, %2;" : "=f"(x), "=f"(y) : "l"(v));
}
__device__ __forceinline__ u64 fma2(u64 a, u64 b, u64 c) {
    u64 d; asm("fma.rn.f32x2 %0, %1, %2, %3;" : "=l"(d) : "l"(a), "l"(b), "l"(c)); return d;
}

// ---------------------------------------------------------------------------
// prep: blocks [0, NB4): 4 G rows each (fused 16-row reduce + matmul).
//       block NB4: P' anchor projections.
// ---------------------------------------------------------------------------
__global__ __launch_bounds__(256) void prep_kernel(
    const float* __restrict__ embeds,
    const int* __restrict__ anchor,
    const float* __restrict__ Wh,
    const float* __restrict__ bias)
{
    __shared__ float Ws[DDIM * 65];   // W2 or W1, [k][d]
    __shared__ float Es[32 * 65];     // E16 rows (4 used) or 32 anchor rows
    const int tid = threadIdx.x;

    if (blockIdx.x < NB4) {
        const int u0 = blockIdx.x * 4;
        // stage W2[k][d]
        #pragma unroll
        for (int i = 0; i < 16; i++) {
            int idx = tid + i * 256;
            int k = idx >> 6, d = idx & 63;
            Ws[k * 65 + d] = Wh[k * 2 * DDIM + DDIM + d];
        }
        // reduce 16 rows -> E16 for 4 u's; thread = (ul, d)
        {
            int d = tid & 63;
            int ul = tid >> 6;              // 0..3
            int u = u0 + ul;
            if (u < NG) {
                const float* src = embeds + (size_t)(16 * u) * DDIM + d;
                float s = 0.f;
                #pragma unroll
                for (int j = 0; j < 16; j++) s += src[j * DDIM];
                Es[ul * 65 + d] = s;
            }
        }
        __syncthreads();
        // matmul: thread = (ul, k): G[u,k] = Es[ul,:] . Ws[k,:]
        {
            int k = tid & 63;
            int ul = tid >> 6;
            int u = u0 + ul;
            if (u < NG) {
                float s = 0.f;
                #pragma unroll 8
                for (int d = 0; d < DDIM; d++)
                    s += Es[ul * 65 + d] * Ws[k * 65 + d];
                g_G[u * DDIM + k] = s * (1.0f / 32.0f) + 0.5f * bias[k];
            }
        }
    } else {
        // P' path
        #pragma unroll
        for (int i = 0; i < 16; i++) {
            int idx = tid + i * 256;
            int k = idx >> 6, d = idx & 63;
            Ws[k * 65 + d] = Wh[k * 2 * DDIM + d];             // W1[k][d]
        }
        #pragma unroll
        for (int i = 0; i < 8; i++) {
            int idx = tid + i * 256;
            int a = idx >> 6, d = idx & 63;
            Es[a * 65 + d] = embeds[(size_t)anchor[a] * DDIM + d];
        }
        __syncthreads();
        int ia = tid >> 3;          // 0..31
        int kbase = (tid & 7) * 8;
        float s[8];
        #pragma unroll
        for (int kk = 0; kk < 8; kk++) s[kk] = 0.f;
        #pragma unroll 8
        for (int d = 0; d < DDIM; d++) {
            float e = Es[ia * 65 + d];
            #pragma unroll
            for (int kk = 0; kk < 8; kk++) s[kk] += e * Ws[(kbase + kk) * 65 + d];
        }
        #pragma unroll
        for (int kk = 0; kk < 8; kk++) {
            float v = s[kk] * (1.0f / 32.0f);
            g_Cdup[ia * 2 * DDIM + 2 * (kbase + kk)]     = v;
            g_Cdup[ia * 2 * DDIM + 2 * (kbase + kk) + 1] = v;
        }
    }
}

// ---------------------------------------------------------------------------
// main: BR=64 rows/block, 128 threads, thread tile = 8 rows x 4 cols.
// out[n,k] = sum_a dists[a,n]*P'[a,k] + G[u1(n),k] + G[u1(n)+1 mod NG, k]
// ---------------------------------------------------------------------------
__global__ __launch_bounds__(THREADS, 8) void main_kernel(
    const float* __restrict__ dists,
    float* __restrict__ out)
{
    __shared__ __align__(16) float smem[AANCH * XS_STRIDE + AANCH * 2 * DDIM]; // 6208 fl
    float* Xs = smem;                              // [32][66]
    float* Cd = smem + AANCH * XS_STRIDE;          // [32][128] dup pairs
    const int tid = threadIdx.x;
    const int row0 = blockIdx.x * BR;

    const int cgp = tid & 15;          // col group: k = cgp + 16q, q=0..3
    const int rg  = tid >> 4;          // row group: rows rg*8 .. rg*8+7
    const int rbase = rg * 8;

    // stage P' dup pairs (L2-resident, 16KB)
    {
        const float4* src = (const float4*)g_Cdup;
        float4* dst = (float4*)Cd;
        #pragma unroll
        for (int i = 0; i < (AANCH * 2 * DDIM / 4) / THREADS; i++)   // 8
            dst[tid + i * THREADS] = src[tid + i * THREADS];
    }
    // stage dists transposed: Xs[a][r] = dists[a*N + row0+r]
    #pragma unroll
    for (int i = 0; i < (AANCH * BR) / THREADS; i++) {               // 16
        int idx = tid + i * THREADS;
        int a = idx >> 6, r = idx & 63;
        int row = row0 + r; if (row >= NTOT) row = NTOT - 1;
        Xs[a * XS_STRIDE + r] = dists[(size_t)a * NTOT + row];
    }

    u64 acc[4][4];
    #pragma unroll
    for (int q = 0; q < 4; q++)
        #pragma unroll
        for (int p = 0; p < 4; p++) acc[q][p] = 0ULL;
    __syncthreads();

    const float* xcol = Xs + rbase;
    const float* ccol = Cd + 2 * cgp;
    #pragma unroll 8
    for (int j = 0; j < AANCH; j++) {
        u64 xv[4];
        #pragma unroll
        for (int p = 0; p < 4; p++)
            xv[p] = *(const u64*)(xcol + j * XS_STRIDE + 2 * p);    // rows (r, r+1)
        #pragma unroll
        for (int q = 0; q < 4; q++) {
            u64 cv = *(const u64*)(ccol + j * 2 * DDIM + 32 * q);   // (c, c) dup
            #pragma unroll
            for (int p = 0; p < 4; p++)
                acc[q][p] = fma2(xv[p], cv, acc[q][p]);
        }
    }
    __syncthreads();

    // transpose through shared
    float* Os = smem;                              // [64][65] = 4160 floats
    #pragma unroll
    for (int q = 0; q < 4; q++) {
        int k = cgp + 16 * q;
        #pragma unroll
        for (int p = 0; p < 4; p++) {
            float lo, hi; unpack2(acc[q][p], lo, hi);
            Os[(rbase + 2 * p) * OS_STRIDE + k] = lo;
            Os[(rbase + 2 * p + 1) * OS_STRIDE + k] = hi;
        }
    }
    __syncthreads();

    // epilogue: add two L2-resident G rows, coalesced store
    int rows_here = NTOT - row0; if (rows_here > BR) rows_here = BR;
    int r = tid >> 6;                  // 0 or 1
    int k = tid & 63;
    int u1 = (2 * (row0 + r)) % NG;    // += 4 per iter, with wrap
    #pragma unroll 4
    for (int i = 0; i < BR / 2; i++, r += 2) {
        if (r < rows_here) {
            int u2 = u1 + 1; if (u2 == NG) u2 = 0;
            out[(size_t)(row0 + r) * DDIM + k] =
                Os[r * OS_STRIDE + k] + g_G[u1 * DDIM + k] + g_G[u2 * DDIM + k];
        }
        u1 += 4; if (u1 >= NG) u1 -= NG;
    }
}

// ---------------------------------------------------------------------------
extern "C" void kernel_launch(void* const* d_in, const int* in_sizes, int n_in,
                              void* d_out, int out_size)
{
    const float* embeds = (const float*)d_in[0];   // (N, D)
    const float* dists  = (const float*)d_in[1];   // (A, N)
    const int*   anchor = (const int*)d_in[2];     // (A,)
    const float* Wh     = (const float*)d_in[3];   // (D, 2D)
    const float* bias   = (const float*)d_in[4];   // (D,)
    float* out = (float*)d_out;
    (void)in_sizes; (void)n_in; (void)out_size;

    prep_kernel<<<NB4 + 1, 256>>>(embeds, anchor, Wh, bias);
    main_kernel<<<(NTOT + BR - 1) / BR, THREADS>>>(dists, out);
}

// round 5
// speedup vs baseline: 1.1484x; 1.0654x over previous
#include <cuda_runtime.h>

#define NTOT 50000
#define AANCH 32
#define DDIM 64
#define NG 3125                    // NTOT/16
#define UB 8                       // u's per prep block
#define NBG ((NG + UB - 1) / UB)   // 391
#define MROWS 128                  // rows per main block (4 warps x 32)

// plain C: g_C[a*64+k] = (1/32) * embeds[anchor[a]] . W1[k,:]
__device__ __align__(16) float g_C[AANCH * DDIM];
// fused pair-G: g_G2[u*64+k] = (E16[u]+E16[(u+1)%NG]).W2[k,:]/32 + b[k]
__device__ __align__(16) float g_G2[NG * DDIM];

typedef unsigned long long u64;

union F4U { float4 f; u64 u[2]; };

__device__ __forceinline__ u64 pack2(float x, float y) {
    u64 r; asm("mov.b64 %0, {%1,%2};" : "=l"(r) : "f"(x), "f"(y)); return r;
}
__device__ __forceinline__ u64 fma2(u64 a, u64 b, u64 c) {
    u64 d; asm("fma.rn.f32x2 %0, %1, %2, %3;" : "=l"(d) : "l"(a), "l"(b), "l"(c)); return d;
}

// ---------------------------------------------------------------------------
// prep: blocks [0,NBG): G2 rows for u0..u0+7 (needs E16 up to u0+8, computed
//       in-block with wrap). block NBG: anchor projections into g_C.
// ---------------------------------------------------------------------------
__global__ __launch_bounds__(256) void prep_kernel(
    const float* __restrict__ embeds,
    const int* __restrict__ anchor,
    const float* __restrict__ Wh,
    const float* __restrict__ bias)
{
    __shared__ float Ws[DDIM * 65];   // W2 (G path) or W1 (P path), [k][d]
    __shared__ float Buf[2304];       // Ps[9][2][64] + E32[8][64]  |  Es[32][65]
    const int t = threadIdx.x;

    if (blockIdx.x < NBG) {
        const int u0 = blockIdx.x * UB;
        // stage W2[k][d] = Wh[k*128 + 64 + d]
        #pragma unroll
        for (int i = 0; i < 16; i++) {
            int idx = t + i * 256;
            int k = idx >> 6, d = idx & 63;
            Ws[k * 65 + d] = Wh[k * 2 * DDIM + DDIM + d];
        }
        // phase A: 8-row partial sums. tasks s: uu=s>>5 (0..8), h=(s>>4)&1, c=s&15
        float* Ps = Buf;                        // [9][2][64]
        for (int s = t; s < (UB + 1) * 32; s += 256) {
            int uu = s >> 5, h = (s >> 4) & 1, c = s & 15;
            int rb = 16 * (u0 + uu);
            if (rb >= NTOT) rb -= NTOT;         // wrap (only u=NG -> rows 0..15 matters)
            const float4* src = (const float4*)(embeds + (size_t)(rb + 8 * h) * DDIM) + c;
            float4 a = make_float4(0.f, 0.f, 0.f, 0.f);
            #pragma unroll
            for (int j = 0; j < 8; j++) {
                float4 v = src[j * 16];
                a.x += v.x; a.y += v.y; a.z += v.z; a.w += v.w;
            }
            float* dst = Ps + (uu * 2 + h) * DDIM + 4 * c;
            dst[0] = a.x; dst[1] = a.y; dst[2] = a.z; dst[3] = a.w;
        }
        __syncthreads();
        // phase B: E32[uu][d] = E16[uu]+E16[uu+1] (4 partials)
        float* E32 = Buf + 1152;                // [8][64]
        for (int s = t; s < UB * DDIM; s += 256) {
            int uu = s >> 6, d = s & 63;
            E32[s] = Ps[(uu * 2) * DDIM + d] + Ps[(uu * 2 + 1) * DDIM + d]
                   + Ps[(uu * 2 + 2) * DDIM + d] + Ps[(uu * 2 + 3) * DDIM + d];
        }
        __syncthreads();
        // phase C: G2[u][k] = E32[uu].Ws[k]/32 + b[k]; thread: k=t&63, uu=(t>>6)*2,+1
        int k = t & 63;
        int uu0 = (t >> 6) * 2;
        float b = __ldg(bias + k);
        #pragma unroll
        for (int ii = 0; ii < 2; ii++) {
            int uu = uu0 + ii;
            float s = 0.f;
            #pragma unroll 16
            for (int d = 0; d < DDIM; d++)
                s += E32[uu * DDIM + d] * Ws[k * 65 + d];
            int u = u0 + uu;
            if (u < NG) g_G2[u * DDIM + k] = s * (1.0f / 32.0f) + b;
        }
    } else {
        // anchor projections -> g_C (plain)
        #pragma unroll
        for (int i = 0; i < 16; i++) {
            int idx = t + i * 256;
            int k = idx >> 6, d = idx & 63;
            Ws[k * 65 + d] = Wh[k * 2 * DDIM + d];            // W1[k][d]
        }
        float* Es = Buf;                                      // [32][65]
        #pragma unroll
        for (int i = 0; i < 8; i++) {
            int idx = t + i * 256;
            int a = idx >> 6, d = idx & 63;
            Es[a * 65 + d] = embeds[(size_t)anchor[a] * DDIM + d];
        }
        __syncthreads();
        int ia = t >> 3;
        int kbase = (t & 7) * 8;
        float s[8];
        #pragma unroll
        for (int kk = 0; kk < 8; kk++) s[kk] = 0.f;
        #pragma unroll 8
        for (int d = 0; d < DDIM; d++) {
            float e = Es[ia * 65 + d];
            #pragma unroll
            for (int kk = 0; kk < 8; kk++) s[kk] += e * Ws[(kbase + kk) * 65 + d];
        }
        #pragma unroll
        for (int kk = 0; kk < 8; kk++)
            g_C[ia * DDIM + kbase + kk] = s[kk] * (1.0f / 32.0f);
    }
}

// ---------------------------------------------------------------------------
// main: warp owns 32 rows (lane = row), 64 k in 32 f32x2 accumulators.
// out[n,k] = sum_a dists[a,n]*C[a,k] + G2[(2n)%NG, k]
// ---------------------------------------------------------------------------
__global__ __launch_bounds__(128) void main_kernel(
    const float* __restrict__ dists,
    float* __restrict__ out)
{
    __shared__ __align__(16) float Cs[AANCH * DDIM];    // 8 KB
    __shared__ __align__(16) float Ot[4 * 32 * 34];     // 17 KB, per-warp tiles
    const int t = threadIdx.x;
    const int lane = t & 31;
    const int wid = t >> 5;
    const int wbase = blockIdx.x * MROWS + wid * 32;

    int n = wbase + lane; if (n >= NTOT) n = NTOT - 1;

    // 32 independent coalesced loads (MLP=32), overlapped with C staging
    float dv[32];
    #pragma unroll
    for (int a = 0; a < 32; a++)
        dv[a] = __ldg(dists + (size_t)a * NTOT + n);

    {
        float4* dst = (float4*)Cs;
        const float4* src = (const float4*)g_C;
        #pragma unroll
        for (int i = 0; i < 4; i++)
            dst[t + i * 128] = src[t + i * 128];
    }
    __syncthreads();

    u64 acc[32];
    #pragma unroll
    for (int q = 0; q < 32; q++) acc[q] = 0ULL;

    const float4* Crow = (const float4*)Cs;
    #pragma unroll
    for (int a = 0; a < 32; a++) {
        u64 bd = pack2(dv[a], dv[a]);
        #pragma unroll
        for (int qq = 0; qq < 16; qq++) {
            F4U cu; cu.f = Crow[a * 16 + qq];               // broadcast LDS.128
            acc[2 * qq]     = fma2(bd, cu.u[0], acc[2 * qq]);
            acc[2 * qq + 1] = fma2(bd, cu.u[1], acc[2 * qq + 1]);
        }
    }

    // epilogue: per-warp transpose tile + fused G2 add, coalesced stores
    float* Ow = Ot + wid * (32 * 34);
    const int rows_valid = NTOT - wbase;       // may be <= 0 for tail warps
    const int u1_0 = (2 * wbase) % NG;
    #pragma unroll
    for (int p = 0; p < 2; p++) {
        __syncwarp();
        #pragma unroll
        for (int qq = 0; qq < 16; qq++)
            *(u64*)(Ow + lane * 34 + 2 * qq) = acc[p * 16 + qq];
        __syncwarp();
        int u1 = u1_0;
        #pragma unroll 4
        for (int r = 0; r < 32; r++) {
            if (r < rows_valid) {
                float v = Ow[r * 34 + lane] + __ldg(g_G2 + u1 * DDIM + p * 32 + lane);
                out[(size_t)(wbase + r) * DDIM + p * 32 + lane] = v;
            }
            u1 += 2; if (u1 >= NG) u1 -= NG;
        }
    }
}

// ---------------------------------------------------------------------------
extern "C" void kernel_launch(void* const* d_in, const int* in_sizes, int n_in,
                              void* d_out, int out_size)
{
    const float* embeds = (const float*)d_in[0];   // (N, D)
    const float* dists  = (const float*)d_in[1];   // (A, N)
    const int*   anchor = (const int*)d_in[2];     // (A,)
    const float* Wh     = (const float*)d_in[3];   // (D, 2D)
    const float* bias   = (const float*)d_in[4];   // (D,)
    float* out = (float*)d_out;
    (void)in_sizes; (void)n_in; (void)out_size;

    prep_kernel<<<NBG + 1, 256>>>(embeds, anchor, Wh, bias);
    main_kernel<<<(NTOT + MROWS - 1) / MROWS, 128>>>(dists, out);
}

// round 6
// speedup vs baseline: 1.1497x; 1.0012x over previous
#include <cuda_runtime.h>

#define NTOT 50000
#define AANCH 32
#define DDIM 64
#define NG 3125                    // NTOT/16
#define UB 4                       // u's per prep block
#define NBG ((NG + UB - 1) / UB)   // 782
#define MROWS 64                   // rows per main block (2 row-groups x 2 col-halves)

// plain C: g_C[a*64+k] = (1/32) * embeds[anchor[a]] . W1[k,:]
__device__ __align__(16) float g_C[AANCH * DDIM];
// pair-G: g_G2[u*64+k] = (E16[u]+E16[(u+1)%NG]).W2[k,:]/32 + b[k]
__device__ __align__(16) float g_G2[NG * DDIM];

typedef unsigned long long u64;
union F4U { float4 f; u64 u[2]; };

__device__ __forceinline__ u64 pack2(float x, float y) {
    u64 r; asm("mov.b64 %0, {%1,%2};" : "=l"(r) : "f"(x), "f"(y)); return r;
}
__device__ __forceinline__ u64 fma2(u64 a, u64 b, u64 c) {
    u64 d; asm("fma.rn.f32x2 %0, %1, %2, %3;" : "=l"(d) : "l"(a), "l"(b), "l"(c)); return d;
}

// ---------------------------------------------------------------------------
// prep: blocks [0,NBG): G2 rows u0..u0+3 (E16 computed in-block, incl. u0+4
//       neighbor with wrap). block NBG: anchor projections into g_C.
// 256 threads.
// ---------------------------------------------------------------------------
__global__ __launch_bounds__(256) void prep_kernel(
    const float* __restrict__ embeds,
    const int* __restrict__ anchor,
    const float* __restrict__ Wh,
    const float* __restrict__ bias)
{
    __shared__ float Wt[DDIM * 65];   // G path: W2t[d*65+k].  P path: W1[k*65+d]
    __shared__ float Buf[2080];       // G: Ps[10][64] + E32[4][64] | P: Es[32][65]
    const int t = threadIdx.x;

    if (blockIdx.x < NBG) {
        const int u0 = blockIdx.x * UB;
        // stage W2 transposed: Wt[d*65 + k] = Wh[k*128 + 64 + d]
        #pragma unroll
        for (int i = 0; i < 4; i++) {
            int idx = t + i * 256;            // 1024 float4 tasks
            int k = idx >> 4, dq = idx & 15;
            float4 v = *(const float4*)(Wh + k * 2 * DDIM + DDIM + 4 * dq);
            Wt[(4 * dq + 0) * 65 + k] = v.x;
            Wt[(4 * dq + 1) * 65 + k] = v.y;
            Wt[(4 * dq + 2) * 65 + k] = v.z;
            Wt[(4 * dq + 3) * 65 + k] = v.w;
        }
        // phase A: 8-row partial sums. 160 tasks: uu 0..4, h 0..1, c 0..15
        float* Ps = Buf;                      // [10][64]
        if (t < (UB + 1) * 32) {
            int uu = t >> 5, h = (t >> 4) & 1, c = t & 15;
            int rb = 16 * (u0 + uu);
            if (rb >= NTOT) rb -= NTOT;       // wrap for the u=NG neighbor
            const float4* src = (const float4*)(embeds + (size_t)(rb + 8 * h) * DDIM) + c;
            float4 a = make_float4(0.f, 0.f, 0.f, 0.f);
            #pragma unroll
            for (int j = 0; j < 8; j++) {
                float4 v = src[j * 16];
                a.x += v.x; a.y += v.y; a.z += v.z; a.w += v.w;
            }
            float* dst = Ps + (uu * 2 + h) * DDIM + 4 * c;
            dst[0] = a.x; dst[1] = a.y; dst[2] = a.z; dst[3] = a.w;
        }
        __syncthreads();
        // phase B: E32[uu][d] = Ps[2uu]+Ps[2uu+1]+Ps[2uu+2]+Ps[2uu+3]
        float* E32 = Buf + 10 * DDIM;         // [4][64]
        {
            int uu = t >> 6, d = t & 63;      // exactly 256 tasks
            E32[uu * DDIM + d] =
                Ps[(2 * uu) * DDIM + d] + Ps[(2 * uu + 1) * DDIM + d] +
                Ps[(2 * uu + 2) * DDIM + d] + Ps[(2 * uu + 3) * DDIM + d];
        }
        __syncthreads();
        // phase C: one output per thread: u = u0 + (t>>6), k = t&63
        {
            int k = t & 63, uu = t >> 6;
            int u = u0 + uu;
            float s = 0.f;
            #pragma unroll 16
            for (int d = 0; d < DDIM; d++)
                s += E32[uu * DDIM + d] * Wt[d * 65 + k];   // broadcast x conflict-free
            if (u < NG)
                g_G2[u * DDIM + k] = s * (1.0f / 32.0f) + __ldg(bias + k);
        }
    } else {
        // anchor projections -> g_C
        #pragma unroll
        for (int i = 0; i < 16; i++) {
            int idx = t + i * 256;
            int k = idx >> 6, d = idx & 63;
            Wt[k * 65 + d] = Wh[k * 2 * DDIM + d];            // W1[k][d]
        }
        float* Es = Buf;                                      // [32][65]
        #pragma unroll
        for (int i = 0; i < 8; i++) {
            int idx = t + i * 256;
            int a = idx >> 6, d = idx & 63;
            Es[a * 65 + d] = embeds[(size_t)anchor[a] * DDIM + d];
        }
        __syncthreads();
        int ia = t >> 3;
        int kbase = (t & 7) * 8;
        float s[8];
        #pragma unroll
        for (int kk = 0; kk < 8; kk++) s[kk] = 0.f;
        #pragma unroll 8
        for (int d = 0; d < DDIM; d++) {
            float e = Es[ia * 65 + d];
            #pragma unroll
            for (int kk = 0; kk < 8; kk++) s[kk] += e * Wt[(kbase + kk) * 65 + d];
        }
        #pragma unroll
        for (int kk = 0; kk < 8; kk++)
            g_C[ia * DDIM + kbase + kk] = s[kk] * (1.0f / 32.0f);
    }
}

// ---------------------------------------------------------------------------
// main: warp = 32 rows x 32 cols (col half per warp). lane = row.
// out[n,k] = sum_a dists[a,n]*C[a,k] + G2[(2n)%NG, k]
// ---------------------------------------------------------------------------
__global__ __launch_bounds__(128) void main_kernel(
    const float* __restrict__ dists,
    float* __restrict__ out)
{
    __shared__ __align__(16) float Cs[AANCH * DDIM];   // 8 KB
    __shared__ __align__(16) float Ot[4 * 32 * 34];    // 17 KB per-warp tiles
    const int t = threadIdx.x;
    const int lane = t & 31;
    const int wid = t >> 5;
    const int half = wid & 1;                 // col half: k in [32h, 32h+32)
    const int rowbase = blockIdx.x * MROWS + (wid >> 1) * 32;

    int n = rowbase + lane; if (n >= NTOT) n = NTOT - 1;

    // issue DRAM loads first (scoreboards survive the barrier below)
    float dv[32];
    #pragma unroll
    for (int a = 0; a < 32; a++)
        dv[a] = __ldg(dists + (size_t)a * NTOT + n);

    {   // stage C
        float4* dst = (float4*)Cs;
        const float4* src = (const float4*)g_C;
        #pragma unroll
        for (int i = 0; i < 4; i++)
            dst[t + i * 128] = src[t + i * 128];
    }
    __syncthreads();

    u64 acc[16];
    #pragma unroll
    for (int q = 0; q < 16; q++) acc[q] = 0ULL;

    const float4* Crow = (const float4*)Cs + half * 8;   // this warp's 32 cols
    #pragma unroll
    for (int a = 0; a < 32; a++) {
        u64 bd = pack2(dv[a], dv[a]);
        #pragma unroll
        for (int qq = 0; qq < 8; qq++) {
            F4U cu; cu.f = Crow[a * 16 + qq];            // LDS.128 broadcast
            acc[2 * qq]     = fma2(bd, cu.u[0], acc[2 * qq]);
            acc[2 * qq + 1] = fma2(bd, cu.u[1], acc[2 * qq + 1]);
        }
    }

    // per-warp transpose, fused G2 add, coalesced stores
    float* Tw = Ot + wid * (32 * 34);
    #pragma unroll
    for (int qq = 0; qq < 16; qq++)
        *(u64*)(Tw + lane * 34 + 2 * qq) = acc[qq];
    __syncwarp();

    const int rows_valid = NTOT - rowbase;
    int u1 = (2 * rowbase) % NG;
    const int kk = half * 32 + lane;
    #pragma unroll 8
    for (int r = 0; r < 32; r++) {
        if (r < rows_valid) {
            float g = __ldg(g_G2 + (size_t)u1 * DDIM + kk);      // L2-resident, coalesced
            out[(size_t)(rowbase + r) * DDIM + kk] = Tw[r * 34 + lane] + g;
        }
        u1 += 2; if (u1 >= NG) u1 -= NG;
    }
}

// ---------------------------------------------------------------------------
extern "C" void kernel_launch(void* const* d_in, const int* in_sizes, int n_in,
                              void* d_out, int out_size)
{
    const float* embeds = (const float*)d_in[0];   // (N, D)
    const float* dists  = (const float*)d_in[1];   // (A, N)
    const int*   anchor = (const int*)d_in[2];     // (A,)
    const float* Wh     = (const float*)d_in[3];   // (D, 2D)
    const float* bias   = (const float*)d_in[4];   // (D,)
    float* out = (float*)d_out;
    (void)in_sizes; (void)n_in; (void)out_size;

    prep_kernel<<<NBG + 1, 256>>>(embeds, anchor, Wh, bias);
    main_kernel<<<(NTOT + MROWS - 1) / MROWS, 128>>>(dists, out);
}

// round 7
// speedup vs baseline: 1.2412x; 1.0795x over previous
#include <cuda_runtime.h>

#define NTOT 50000
#define AANCH 32
#define DDIM 64
#define NG 3125                    // NTOT/16
#define UB 4                       // u's per prep block
#define NBG ((NG + UB - 1) / UB)   // 782
#define MROWS 64                   // rows per main block (all 4 warps share rows)

// plain C: g_C[a*64+k] = (1/32) * embeds[anchor[a]] . W1[k,:]
__device__ __align__(16) float g_C[AANCH * DDIM];
// pair-G: g_G2[u*64+k] = (E16[u]+E16[(u+1)%NG]).W2[k,:]/32 + b[k]
__device__ __align__(16) float g_G2[NG * DDIM];

typedef unsigned long long u64;
union F4U { float4 f; u64 u[2]; };

__device__ __forceinline__ u64 pack2(float x, float y) {
    u64 r; asm("mov.b64 %0, {%1,%2};" : "=l"(r) : "f"(x), "f"(y)); return r;
}
__device__ __forceinline__ void unpack2(u64 v, float& x, float& y) {
    asm("mov.b64 {%0,%1}, %2;" : "=f"(x), "=f"(y) : "l"(v));
}
__device__ __forceinline__ u64 fma2(u64 a, u64 b, u64 c) {
    u64 d; asm("fma.rn.f32x2 %0, %1, %2, %3;" : "=l"(d) : "l"(a), "l"(b), "l"(c)); return d;
}

// ---------------------------------------------------------------------------
// prep: blocks [0,NBG): G2 rows u0..u0+3 (E16 computed in-block incl. the
//       u0+4 neighbor with wrap). block NBG: anchor projections into g_C.
// ---------------------------------------------------------------------------
__global__ __launch_bounds__(256) void prep_kernel(
    const float* __restrict__ embeds,
    const int* __restrict__ anchor,
    const float* __restrict__ Wh,
    const float* __restrict__ bias)
{
    __shared__ float Wt[DDIM * 65];   // G path: W2t[d*65+k].  P path: W1[k*65+d]
    __shared__ float Buf[2080];       // G: Ps[10][64] + E32[4][64] | P: Es[32][65]
    const int t = threadIdx.x;

    if (blockIdx.x < NBG) {
        const int u0 = blockIdx.x * UB;
        // stage W2 transposed: Wt[d*65 + k] = Wh[k*128 + 64 + d]
        #pragma unroll
        for (int i = 0; i < 4; i++) {
            int idx = t + i * 256;
            int k = idx >> 4, dq = idx & 15;
            float4 v = *(const float4*)(Wh + k * 2 * DDIM + DDIM + 4 * dq);
            Wt[(4 * dq + 0) * 65 + k] = v.x;
            Wt[(4 * dq + 1) * 65 + k] = v.y;
            Wt[(4 * dq + 2) * 65 + k] = v.z;
            Wt[(4 * dq + 3) * 65 + k] = v.w;
        }
        // phase A: 8-row partial sums (160 tasks)
        float* Ps = Buf;                      // [10][64]
        if (t < (UB + 1) * 32) {
            int uu = t >> 5, h = (t >> 4) & 1, c = t & 15;
            int rb = 16 * (u0 + uu);
            if (rb >= NTOT) rb -= NTOT;
            const float4* src = (const float4*)(embeds + (size_t)(rb + 8 * h) * DDIM) + c;
            float4 a = make_float4(0.f, 0.f, 0.f, 0.f);
            #pragma unroll
            for (int j = 0; j < 8; j++) {
                float4 v = src[j * 16];
                a.x += v.x; a.y += v.y; a.z += v.z; a.w += v.w;
            }
            float* dst = Ps + (uu * 2 + h) * DDIM + 4 * c;
            dst[0] = a.x; dst[1] = a.y; dst[2] = a.z; dst[3] = a.w;
        }
        __syncthreads();
        // phase B: E32[uu][d]
        float* E32 = Buf + 10 * DDIM;         // [4][64]
        {
            int uu = t >> 6, d = t & 63;
            E32[uu * DDIM + d] =
                Ps[(2 * uu) * DDIM + d] + Ps[(2 * uu + 1) * DDIM + d] +
                Ps[(2 * uu + 2) * DDIM + d] + Ps[(2 * uu + 3) * DDIM + d];
        }
        __syncthreads();
        // phase C: one output/thread
        {
            int k = t & 63, uu = t >> 6;
            int u = u0 + uu;
            float s = 0.f;
            #pragma unroll 16
            for (int d = 0; d < DDIM; d++)
                s += E32[uu * DDIM + d] * Wt[d * 65 + k];
            if (u < NG)
                g_G2[u * DDIM + k] = s * (1.0f / 32.0f) + __ldg(bias + k);
        }
    } else {
        // anchor projections -> g_C
        #pragma unroll
        for (int i = 0; i < 16; i++) {
            int idx = t + i * 256;
            int k = idx >> 6, d = idx & 63;
            Wt[k * 65 + d] = Wh[k * 2 * DDIM + d];
        }
        float* Es = Buf;                       // [32][65]
        #pragma unroll
        for (int i = 0; i < 8; i++) {
            int idx = t + i * 256;
            int a = idx >> 6, d = idx & 63;
            Es[a * 65 + d] = embeds[(size_t)anchor[a] * DDIM + d];
        }
        __syncthreads();
        int ia = t >> 3;
        int kbase = (t & 7) * 8;
        float s[8];
        #pragma unroll
        for (int kk = 0; kk < 8; kk++) s[kk] = 0.f;
        #pragma unroll 8
        for (int d = 0; d < DDIM; d++) {
            float e = Es[ia * 65 + d];
            #pragma unroll
            for (int kk = 0; kk < 8; kk++) s[kk] += e * Wt[(kbase + kk) * 65 + d];
        }
        #pragma unroll
        for (int kk = 0; kk < 8; kk++)
            g_C[ia * DDIM + kbase + kk] = s[kk] * (1.0f / 32.0f);
    }
}

// ---------------------------------------------------------------------------
// main: block = 64 rows x 64 cols; warp = 64 rows x 16 cols (2 row-sets/lane,
// C loads reused by both sets -> 4 LDS.128 per a for 32 FFMA2).
// out[n,k] = sum_a dists[a,n]*C[a,k] + G2[(2n)%NG, k]
// ---------------------------------------------------------------------------
__global__ __launch_bounds__(128) void main_kernel(
    const float* __restrict__ dists,
    float* __restrict__ out)
{
    __shared__ __align__(16) float Cs[AANCH * DDIM];   // 8 KB
    __shared__ __align__(16) float Os[MROWS * 65];     // 16.25 KB
    const int t = threadIdx.x;
    const int lane = t & 31;
    const int wid = t >> 5;
    const int c0 = wid * 16;                  // this warp's 16 cols
    const int rowbase = blockIdx.x * MROWS;

    int n0 = rowbase + lane;      if (n0 >= NTOT) n0 = NTOT - 1;
    int n1 = rowbase + 32 + lane; if (n1 >= NTOT) n1 = NTOT - 1;

    // 64 independent coalesced DRAM loads per lane (issued before the barrier)
    float dv0[32], dv1[32];
    #pragma unroll
    for (int a = 0; a < 32; a++) dv0[a] = __ldg(dists + (size_t)a * NTOT + n0);
    #pragma unroll
    for (int a = 0; a < 32; a++) dv1[a] = __ldg(dists + (size_t)a * NTOT + n1);

    {   // stage C
        float4* dst = (float4*)Cs;
        const float4* src = (const float4*)g_C;
        #pragma unroll
        for (int i = 0; i < 4; i++)
            dst[t + i * 128] = src[t + i * 128];
    }
    __syncthreads();

    u64 acc0[8], acc1[8];
    #pragma unroll
    for (int q = 0; q < 8; q++) { acc0[q] = 0ULL; acc1[q] = 0ULL; }

    const float4* Crow = (const float4*)Cs + (c0 >> 2);
    #pragma unroll
    for (int a = 0; a < 32; a++) {
        u64 b0 = pack2(dv0[a], dv0[a]);
        u64 b1 = pack2(dv1[a], dv1[a]);
        #pragma unroll
        for (int qq = 0; qq < 4; qq++) {
            F4U cu; cu.f = Crow[a * 16 + qq];              // broadcast LDS.128
            acc0[2 * qq]     = fma2(b0, cu.u[0], acc0[2 * qq]);
            acc0[2 * qq + 1] = fma2(b0, cu.u[1], acc0[2 * qq + 1]);
            acc1[2 * qq]     = fma2(b1, cu.u[0], acc1[2 * qq]);
            acc1[2 * qq + 1] = fma2(b1, cu.u[1], acc1[2 * qq + 1]);
        }
    }

    // block transpose tile, scalar STS stride 65 (conflict-free)
    #pragma unroll
    for (int qq = 0; qq < 8; qq++) {
        float x, y;
        unpack2(acc0[qq], x, y);
        Os[lane * 65 + c0 + 2 * qq]     = x;
        Os[lane * 65 + c0 + 2 * qq + 1] = y;
        unpack2(acc1[qq], x, y);
        Os[(32 + lane) * 65 + c0 + 2 * qq]     = x;
        Os[(32 + lane) * 65 + c0 + 2 * qq + 1] = y;
    }
    __syncthreads();

    // fused G2 add + coalesced store: thread = fixed k, rows t>>6 + 2i
    const int rows_valid = NTOT - rowbase;
    const int k = t & 63;
    int r = t >> 6;
    int u1 = (2 * (rowbase + r)) % NG;
    #pragma unroll 8
    for (int i = 0; i < MROWS / 2; i++, r += 2) {
        if (r < rows_valid) {
            float g = __ldg(g_G2 + (size_t)u1 * DDIM + k);   // L2-resident, coalesced
            out[(size_t)(rowbase + r) * DDIM + k] = Os[r * 65 + k] + g;
        }
        u1 += 4; if (u1 >= NG) u1 -= NG;
    }
}

// ---------------------------------------------------------------------------
extern "C" void kernel_launch(void* const* d_in, const int* in_sizes, int n_in,
                              void* d_out, int out_size)
{
    const float* embeds = (const float*)d_in[0];   // (N, D)
    const float* dists  = (const float*)d_in[1];   // (A, N)
    const int*   anchor = (const int*)d_in[2];     // (A,)
    const float* Wh     = (const float*)d_in[3];   // (D, 2D)
    const float* bias   = (const float*)d_in[4];   // (D,)
    float* out = (float*)d_out;
    (void)in_sizes; (void)n_in; (void)out_size;

    prep_kernel<<<NBG + 1, 256>>>(embeds, anchor, Wh, bias);
    main_kernel<<<(NTOT + MROWS - 1) / MROWS, 128>>>(dists, out);
}